// round 15
// baseline (speedup 1.0000x reference)
#include <cuda_runtime.h>
#include <cuda_fp16.h>
#include <cstdint>

// Problem constants
#define B_SZ 256
#define W_SZ 4096
#define L_SZ 16
#define K_SZ 8

// Ping-pong activation scratch, fp16, transposed layout: h_t[n][b] (b fast).
// 2 * 4096 * 256 * 2B = 4 MB  -> fully L2-resident.
__device__ __half g_h[2][(size_t)W_SZ * B_SZ];

// Detected element width of inv_mask input: 1 (bool/uint8) or 4 (int32/float32).
__device__ int g_inv_width;

// ---------------------------------------------------------------------------
// Kernel 1: fused prior + transpose (+ PARALLEL inv width detection, block 0).
//   h_t[n][b] = (half) relu(obs[b][n] * pw[n] + pb[n])
// Tile 64b x 32n; loads fully coalesced (128B/warp); stores are half2 ->
// 128B full-line warp stores. pw/pb loads are warp-uniform.
// ---------------------------------------------------------------------------
__global__ void __launch_bounds__(256) prior_transpose_kernel(
    const float* __restrict__ obs,
    const float* __restrict__ pw,
    const float* __restrict__ pb,
    const unsigned char* __restrict__ inv)
{
    const int tx = threadIdx.x;   // 0..31
    const int ty = threadIdx.y;   // 0..7

    if (blockIdx.x == 0 && blockIdx.y == 0) {
        const int t = ty * 32 + tx;                            // 0..255
        const int pred = (inv[t * 4 + 1] != 0) ? 1 : 0;        // coalesced
        const int any = __syncthreads_or(pred);
        if (t == 0) g_inv_width = any ? 1 : 4;
    }

    __shared__ float tile[64][33];
    const int n0 = blockIdx.x * 32;
    const int b0 = blockIdx.y * 64;

#pragma unroll
    for (int jj = 0; jj < 8; jj++) {
        int bl = ty + jj * 8;
        tile[bl][tx] = obs[(size_t)(b0 + bl) * W_SZ + n0 + tx];  // tile[b_local][n_local]
    }
    __syncthreads();
#pragma unroll
    for (int j = 0; j < 4; j++) {
        int nl = ty + j * 8;
        int n  = n0 + nl;
        float wN = __ldg(pw + n);   // warp-uniform
        float bN = __ldg(pb + n);
        float v0 = fmaxf(fmaf(tile[2 * tx][nl],     wN, bN), 0.0f);
        float v1 = fmaxf(fmaf(tile[2 * tx + 1][nl], wN, bN), 0.0f);
        __half2 h2 = __floats2half2_rn(v0, v1);
        *reinterpret_cast<__half2*>(g_h[0] + (size_t)n * B_SZ + b0 + 2 * tx) = h2;
    }
#if __CUDA_ARCH__ >= 900
    cudaTriggerProgrammaticLaunchCompletion();
#endif
}

// ---------------------------------------------------------------------------
// Shared level math: PDL prologue loads params + gather addresses; post-sync
// all 8 LDG.128 gathers issue back-to-back (MLP=8), then convert+FMA.
// For lvl >= 1 the inv_mask (pure input) and g_inv_width (written by the
// prior kernel, which is guaranteed complete before any level>=1 prologue
// starts: level-1 CTAs launch only after all level-0 CTAs passed their
// grid-sync on the prior kernel) are read in the PROLOGUE, shortening the
// post-gather dependent tail. Level 0 reads them post-sync.
// ---------------------------------------------------------------------------
__device__ __forceinline__ void level_math(
    int src, int lvl, int n, int b,
    const float*         __restrict__ weights,
    const float*         __restrict__ biases,
    const int*           __restrict__ parents,
    const unsigned char* __restrict__ inv_base,
    float acc[8])
{
    // ---- PDL prologue: input-only loads + address math ----
    const int4*   pp = reinterpret_cast<const int4*>(parents + (size_t)n * K_SZ);
    const float4* wp = reinterpret_cast<const float4*>(weights + (size_t)n * K_SZ);
    int4   p0 = __ldg(pp);
    int4   p1 = __ldg(pp + 1);
    float4 w0 = __ldg(wp);
    float4 w1 = __ldg(wp + 1);
    float  bb = __ldg(biases + n);
    float  sw = ((w0.x + w0.y) + (w0.z + w0.w)) + ((w1.x + w1.y) + (w1.z + w1.w));
    float  base_inv = bb + sw;

    bool iv = false;
    if (lvl > 0) {
        if (g_inv_width == 4) {
            const unsigned* iw = reinterpret_cast<const unsigned*>(inv_base);
            iv = (__ldg(iw + (size_t)lvl * W_SZ + n) != 0u);
        } else {
            iv = (__ldg(inv_base + (size_t)lvl * W_SZ + n) != 0);
        }
    }

    const __half* hb = g_h[src] + b;
    const int4* a0 = reinterpret_cast<const int4*>(hb + (((size_t)p0.x) << 8));
    const int4* a1 = reinterpret_cast<const int4*>(hb + (((size_t)p0.y) << 8));
    const int4* a2 = reinterpret_cast<const int4*>(hb + (((size_t)p0.z) << 8));
    const int4* a3 = reinterpret_cast<const int4*>(hb + (((size_t)p0.w) << 8));
    const int4* a4 = reinterpret_cast<const int4*>(hb + (((size_t)p1.x) << 8));
    const int4* a5 = reinterpret_cast<const int4*>(hb + (((size_t)p1.y) << 8));
    const int4* a6 = reinterpret_cast<const int4*>(hb + (((size_t)p1.z) << 8));
    const int4* a7 = reinterpret_cast<const int4*>(hb + (((size_t)p1.w) << 8));

#if __CUDA_ARCH__ >= 900
    cudaGridDependencySynchronize();   // previous level's stores now visible
#endif

    // ---- all 8 gathers in flight before any consumption (MLP = 8) ----
    int4 r0 = __ldg(a0);
    int4 r1 = __ldg(a1);
    int4 r2 = __ldg(a2);
    int4 r3 = __ldg(a3);
    int4 r4 = __ldg(a4);
    int4 r5 = __ldg(a5);
    int4 r6 = __ldg(a6);
    int4 r7 = __ldg(a7);

    if (lvl == 0) {
        // g_inv_width is written by the prior kernel -> only safe post-sync
        // here; the short load chain hides under the gathers above.
        if (g_inv_width == 4) {
            const unsigned* iw = reinterpret_cast<const unsigned*>(inv_base);
            iv = (__ldg(iw + n) != 0u);
        } else {
            iv = (__ldg(inv_base + n) != 0);
        }
    }

#pragma unroll
    for (int i = 0; i < 8; i++) acc[i] = 0.0f;

#define ACCUM(RAW, WV)                                                         \
    {                                                                          \
        float2 f0 = __half22float2(*reinterpret_cast<__half2*>(&(RAW).x));     \
        float2 f1 = __half22float2(*reinterpret_cast<__half2*>(&(RAW).y));     \
        float2 f2 = __half22float2(*reinterpret_cast<__half2*>(&(RAW).z));     \
        float2 f3 = __half22float2(*reinterpret_cast<__half2*>(&(RAW).w));     \
        acc[0] = fmaf((WV), f0.x, acc[0]); acc[1] = fmaf((WV), f0.y, acc[1]);  \
        acc[2] = fmaf((WV), f1.x, acc[2]); acc[3] = fmaf((WV), f1.y, acc[3]);  \
        acc[4] = fmaf((WV), f2.x, acc[4]); acc[5] = fmaf((WV), f2.y, acc[5]);  \
        acc[6] = fmaf((WV), f3.x, acc[6]); acc[7] = fmaf((WV), f3.y, acc[7]);  \
    }
    ACCUM(r0, w0.x)
    ACCUM(r1, w0.y)
    ACCUM(r2, w0.z)
    ACCUM(r3, w0.w)
    ACCUM(r4, w1.x)
    ACCUM(r5, w1.y)
    ACCUM(r6, w1.z)
    ACCUM(r7, w1.w)
#undef ACCUM

    //  Σ w*(1-x) + b == (b + Σw) - Σ w*x
    float basev = iv ? base_inv : bb;
    float sgn   = iv ? -1.0f : 1.0f;

#pragma unroll
    for (int i = 0; i < 8; i++) acc[i] = fmaxf(fmaf(sgn, acc[i], basev), 0.0f);
}

// ---------------------------------------------------------------------------
// Kernel 2a: intermediate scan level (0..13) — stores fp16 to ping-pong.
// 128-thread CTAs (4 warps) x 1024 blocks: the measured optimum
// (256thr: 43.5us, 128thr: 41.4us, 64thr: 53.7us).
// ---------------------------------------------------------------------------
__global__ void __launch_bounds__(128, 8) level_kernel(
    int src,
    int lvl,
    const float*         __restrict__ weights,
    const float*         __restrict__ biases,
    const int*           __restrict__ parents,
    const unsigned char* __restrict__ inv_base)
{
    const int gid = blockIdx.x * 128 + threadIdx.x;
    const int n   = gid >> 5;          // 32 threads per n
    const int b   = (gid & 31) << 3;   // lane's 8-wide batch slice

    float acc[8];
    level_math(src, lvl, n, b, weights, biases, parents, inv_base, acc);

    __half2 o0 = __floats2half2_rn(acc[0], acc[1]);
    __half2 o1 = __floats2half2_rn(acc[2], acc[3]);
    __half2 o2 = __floats2half2_rn(acc[4], acc[5]);
    __half2 o3 = __floats2half2_rn(acc[6], acc[7]);
    int4 outv;
    outv.x = *reinterpret_cast<int*>(&o0);
    outv.y = *reinterpret_cast<int*>(&o1);
    outv.z = *reinterpret_cast<int*>(&o2);
    outv.w = *reinterpret_cast<int*>(&o3);
    *reinterpret_cast<int4*>(g_h[src ^ 1] + (size_t)n * B_SZ + b) = outv;

#if __CUDA_ARCH__ >= 900
    cudaTriggerProgrammaticLaunchCompletion();
#endif
}

// ---------------------------------------------------------------------------
// Kernel 2b: FINAL level (14) — fused output transpose.
// CTA covers 8 consecutive n. fp32 results staged in a bank-conflict-free
// smem tile (pitch 260), then written to out[b][n] as full 32B sectors.
// ---------------------------------------------------------------------------
#define TILE_PITCH 260
__global__ void __launch_bounds__(256, 4) level_out_kernel(
    int src,
    int lvl,
    const float*         __restrict__ weights,
    const float*         __restrict__ biases,
    const int*           __restrict__ parents,
    const unsigned char* __restrict__ inv_base,
    float* __restrict__ out)
{
    __shared__ float tile[8 * TILE_PITCH];

    const int lane = threadIdx.x & 31;
    const int w    = threadIdx.x >> 5;         // warp id in CTA = local n
    const int n0   = blockIdx.x * 8;
    const int n    = n0 + w;
    const int b    = lane << 3;

    float acc[8];
    level_math(src, lvl, n, b, weights, biases, parents, inv_base, acc);

    float* tp = tile + w * TILE_PITCH + b;
    *reinterpret_cast<float4*>(tp)     = make_float4(acc[0], acc[1], acc[2], acc[3]);
    *reinterpret_cast<float4*>(tp + 4) = make_float4(acc[4], acc[5], acc[6], acc[7]);
    __syncthreads();

    const int nn = lane & 7;          // 0..7  (n offset)
    const int bq = lane >> 3;         // 0..3  (b offset within group)
#pragma unroll
    for (int j = 0; j < 8; j++) {
        int bb = w * 32 + j * 4 + bq;
        float v = tile[nn * TILE_PITCH + bb];
        out[(size_t)bb * W_SZ + n0 + nn] = v;
    }
}

// ---------------------------------------------------------------------------
// Launch: prior -> 14 intermediate levels -> fused final level, PDL-chained.
// ---------------------------------------------------------------------------
extern "C" void kernel_launch(void* const* d_in, const int* in_sizes, int n_in,
                              void* d_out, int out_size)
{
    const float*         obs     = (const float*)d_in[0];         // [B, W]
    const float*         pw      = (const float*)d_in[1];         // [W]
    const float*         pb      = (const float*)d_in[2];         // [W]
    const float*         weights = (const float*)d_in[3];         // [L-1, W, K]
    const float*         biases  = (const float*)d_in[4];         // [L-1, W]
    const int*           parents = (const int*)d_in[5];           // [L-1, W, K]
    const unsigned char* inv     = (const unsigned char*)d_in[6]; // [L-1, W]
    float*               out     = (float*)d_out;                 // [B, W]

    (void)in_sizes; (void)n_in; (void)out_size;

    // Prior + transpose into g_h[0] (also detects inv_mask element width)
    prior_transpose_kernel<<<dim3(W_SZ / 32, B_SZ / 64), dim3(32, 8)>>>(obs, pw, pb, inv);

    cudaLaunchAttribute attrs[1];
    attrs[0].id = cudaLaunchAttributeProgrammaticStreamSerialization;
    attrs[0].val.programmaticStreamSerializationAllowed = 1;

    // Levels 0..13: ping-pong g_h[0] <-> g_h[1], PDL-chained, 128-thr CTAs.
    const int blocks = (W_SZ * 32) / 128;  // 1024
    for (int l = 0; l < L_SZ - 2; l++) {
        cudaLaunchConfig_t cfg = {};
        cfg.gridDim  = dim3(blocks, 1, 1);
        cfg.blockDim = dim3(128, 1, 1);
        cfg.dynamicSmemBytes = 0;
        cfg.stream = 0;
        cfg.attrs = attrs;
        cfg.numAttrs = 1;
        cudaLaunchKernelEx(&cfg, level_kernel,
            l & 1, l,
            (const float*)(weights + (size_t)l * W_SZ * K_SZ),
            (const float*)(biases  + (size_t)l * W_SZ),
            (const int*)(parents + (size_t)l * W_SZ * K_SZ),
            (const unsigned char*)inv);
    }

    // Level 14: fused final level + output transpose (fp32, direct to out).
    {
        const int l = L_SZ - 2;  // 14
        cudaLaunchConfig_t cfg = {};
        cfg.gridDim  = dim3(W_SZ / 8, 1, 1);   // 512 CTAs x 8 warps
        cfg.blockDim = dim3(256, 1, 1);
        cfg.dynamicSmemBytes = 0;
        cfg.stream = 0;
        cfg.attrs = attrs;
        cfg.numAttrs = 1;
        cudaLaunchKernelEx(&cfg, level_out_kernel,
            l & 1, l,
            (const float*)(weights + (size_t)l * W_SZ * K_SZ),
            (const float*)(biases  + (size_t)l * W_SZ),
            (const int*)(parents + (size_t)l * W_SZ * K_SZ),
            (const unsigned char*)inv,
            out);
    }
}

// round 16
// speedup vs baseline: 1.4517x; 1.4517x over previous
#include <cuda_runtime.h>
#include <cuda_fp16.h>
#include <cstdint>

// Problem constants
#define B_SZ 256
#define W_SZ 4096
#define L_SZ 16
#define K_SZ 8

// Ping-pong activation scratch, fp16, transposed layout: h_t[n][b] (b fast).
// 2 * 4096 * 256 * 2B = 4 MB  -> fully L2-resident.
__device__ __half g_h[2][(size_t)W_SZ * B_SZ];

// Detected element width of inv_mask input: 1 (bool/uint8) or 4 (int32/float32).
__device__ int g_inv_width;

// ---------------------------------------------------------------------------
// Kernel 1: fused prior + transpose (+ PARALLEL inv width detection, block 0).
//   h_t[n][b] = (half) relu(obs[b][n] * pw[n] + pb[n])
// Tile 64b x 32n; loads fully coalesced (128B/warp); stores are half2 ->
// 128B full-line warp stores. pw/pb loads are warp-uniform.
// ---------------------------------------------------------------------------
__global__ void __launch_bounds__(256) prior_transpose_kernel(
    const float* __restrict__ obs,
    const float* __restrict__ pw,
    const float* __restrict__ pb,
    const unsigned char* __restrict__ inv)
{
    const int tx = threadIdx.x;   // 0..31
    const int ty = threadIdx.y;   // 0..7

    if (blockIdx.x == 0 && blockIdx.y == 0) {
        const int t = ty * 32 + tx;                            // 0..255
        const int pred = (inv[t * 4 + 1] != 0) ? 1 : 0;        // coalesced
        const int any = __syncthreads_or(pred);
        if (t == 0) g_inv_width = any ? 1 : 4;
    }

    __shared__ float tile[64][33];
    const int n0 = blockIdx.x * 32;
    const int b0 = blockIdx.y * 64;

#pragma unroll
    for (int jj = 0; jj < 8; jj++) {
        int bl = ty + jj * 8;
        tile[bl][tx] = obs[(size_t)(b0 + bl) * W_SZ + n0 + tx];  // tile[b_local][n_local]
    }
    __syncthreads();
#pragma unroll
    for (int j = 0; j < 4; j++) {
        int nl = ty + j * 8;
        int n  = n0 + nl;
        float wN = __ldg(pw + n);   // warp-uniform
        float bN = __ldg(pb + n);
        float v0 = fmaxf(fmaf(tile[2 * tx][nl],     wN, bN), 0.0f);
        float v1 = fmaxf(fmaf(tile[2 * tx + 1][nl], wN, bN), 0.0f);
        __half2 h2 = __floats2half2_rn(v0, v1);
        *reinterpret_cast<__half2*>(g_h[0] + (size_t)n * B_SZ + b0 + 2 * tx) = h2;
    }
#if __CUDA_ARCH__ >= 900
    cudaTriggerProgrammaticLaunchCompletion();
#endif
}

// ---------------------------------------------------------------------------
// Shared level math (R13-proven shape): PDL prologue is a FLAT burst of
// independent input-only loads + address math; post-sync all 8 LDG.128
// gathers issue back-to-back (MLP=8); the inv/g_inv_width chain is resolved
// post-sync where it hides under the in-flight gathers.
// ---------------------------------------------------------------------------
__device__ __forceinline__ void level_math(
    int src, int lvl, int n, int b,
    const float*         __restrict__ weights,
    const float*         __restrict__ biases,
    const int*           __restrict__ parents,
    const unsigned char* __restrict__ inv_base,
    float acc[8])
{
    // ---- PDL prologue: input-only loads + address math ----
    const int4*   pp = reinterpret_cast<const int4*>(parents + (size_t)n * K_SZ);
    const float4* wp = reinterpret_cast<const float4*>(weights + (size_t)n * K_SZ);
    int4   p0 = __ldg(pp);
    int4   p1 = __ldg(pp + 1);
    float4 w0 = __ldg(wp);
    float4 w1 = __ldg(wp + 1);
    float  bb = __ldg(biases + n);
    float  sw = ((w0.x + w0.y) + (w0.z + w0.w)) + ((w1.x + w1.y) + (w1.z + w1.w));
    float  base_inv = bb + sw;

    const __half* hb = g_h[src] + b;
    const int4* a0 = reinterpret_cast<const int4*>(hb + (((size_t)p0.x) << 8));
    const int4* a1 = reinterpret_cast<const int4*>(hb + (((size_t)p0.y) << 8));
    const int4* a2 = reinterpret_cast<const int4*>(hb + (((size_t)p0.z) << 8));
    const int4* a3 = reinterpret_cast<const int4*>(hb + (((size_t)p0.w) << 8));
    const int4* a4 = reinterpret_cast<const int4*>(hb + (((size_t)p1.x) << 8));
    const int4* a5 = reinterpret_cast<const int4*>(hb + (((size_t)p1.y) << 8));
    const int4* a6 = reinterpret_cast<const int4*>(hb + (((size_t)p1.z) << 8));
    const int4* a7 = reinterpret_cast<const int4*>(hb + (((size_t)p1.w) << 8));

#if __CUDA_ARCH__ >= 900
    cudaGridDependencySynchronize();   // previous level's stores now visible
#endif

    // ---- all 8 gathers in flight before any consumption (MLP = 8) ----
    int4 r0 = __ldg(a0);
    int4 r1 = __ldg(a1);
    int4 r2 = __ldg(a2);
    int4 r3 = __ldg(a3);
    int4 r4 = __ldg(a4);
    int4 r5 = __ldg(a5);
    int4 r6 = __ldg(a6);
    int4 r7 = __ldg(a7);

#pragma unroll
    for (int i = 0; i < 8; i++) acc[i] = 0.0f;

#define ACCUM(RAW, WV)                                                         \
    {                                                                          \
        float2 f0 = __half22float2(*reinterpret_cast<__half2*>(&(RAW).x));     \
        float2 f1 = __half22float2(*reinterpret_cast<__half2*>(&(RAW).y));     \
        float2 f2 = __half22float2(*reinterpret_cast<__half2*>(&(RAW).z));     \
        float2 f3 = __half22float2(*reinterpret_cast<__half2*>(&(RAW).w));     \
        acc[0] = fmaf((WV), f0.x, acc[0]); acc[1] = fmaf((WV), f0.y, acc[1]);  \
        acc[2] = fmaf((WV), f1.x, acc[2]); acc[3] = fmaf((WV), f1.y, acc[3]);  \
        acc[4] = fmaf((WV), f2.x, acc[4]); acc[5] = fmaf((WV), f2.y, acc[5]);  \
        acc[6] = fmaf((WV), f3.x, acc[6]); acc[7] = fmaf((WV), f3.y, acc[7]);  \
    }
    ACCUM(r0, w0.x)
    ACCUM(r1, w0.y)
    ACCUM(r2, w0.z)
    ACCUM(r3, w0.w)
    ACCUM(r4, w1.x)
    ACCUM(r5, w1.y)
    ACCUM(r6, w1.z)
    ACCUM(r7, w1.w)
#undef ACCUM

    // inv resolution (post-sync; hides under the gathers above).
    bool iv;
    if (g_inv_width == 4) {
        const unsigned* iw = reinterpret_cast<const unsigned*>(inv_base);
        iv = (__ldg(iw + (size_t)lvl * W_SZ + n) != 0u);
    } else {
        iv = (__ldg(inv_base + (size_t)lvl * W_SZ + n) != 0);
    }
    //  Σ w*(1-x) + b == (b + Σw) - Σ w*x
    float basev = iv ? base_inv : bb;
    float sgn   = iv ? -1.0f : 1.0f;

#pragma unroll
    for (int i = 0; i < 8; i++) acc[i] = fmaxf(fmaf(sgn, acc[i], basev), 0.0f);
}

// ---------------------------------------------------------------------------
// Kernel 2a: intermediate scan level (0..13) — stores fp16 to ping-pong.
// 128-thread CTAs (4 warps) x 1024 blocks: the measured optimum
// (256thr: 43.5us, 128thr: 41.4us, 64thr: 53.7us).
// ---------------------------------------------------------------------------
__global__ void __launch_bounds__(128, 8) level_kernel(
    int src,
    int lvl,
    const float*         __restrict__ weights,
    const float*         __restrict__ biases,
    const int*           __restrict__ parents,
    const unsigned char* __restrict__ inv_base)
{
    const int gid = blockIdx.x * 128 + threadIdx.x;
    const int n   = gid >> 5;          // 32 threads per n
    const int b   = (gid & 31) << 3;   // lane's 8-wide batch slice

    float acc[8];
    level_math(src, lvl, n, b, weights, biases, parents, inv_base, acc);

    __half2 o0 = __floats2half2_rn(acc[0], acc[1]);
    __half2 o1 = __floats2half2_rn(acc[2], acc[3]);
    __half2 o2 = __floats2half2_rn(acc[4], acc[5]);
    __half2 o3 = __floats2half2_rn(acc[6], acc[7]);
    int4 outv;
    outv.x = *reinterpret_cast<int*>(&o0);
    outv.y = *reinterpret_cast<int*>(&o1);
    outv.z = *reinterpret_cast<int*>(&o2);
    outv.w = *reinterpret_cast<int*>(&o3);
    *reinterpret_cast<int4*>(g_h[src ^ 1] + (size_t)n * B_SZ + b) = outv;

#if __CUDA_ARCH__ >= 900
    cudaTriggerProgrammaticLaunchCompletion();
#endif
}

// ---------------------------------------------------------------------------
// Kernel 2b: FINAL level (14) — fused output transpose.
// CTA covers 8 consecutive n. fp32 results staged in a bank-conflict-free
// smem tile (pitch 260), then written to out[b][n] as full 32B sectors.
// ---------------------------------------------------------------------------
#define TILE_PITCH 260
__global__ void __launch_bounds__(256, 4) level_out_kernel(
    int src,
    int lvl,
    const float*         __restrict__ weights,
    const float*         __restrict__ biases,
    const int*           __restrict__ parents,
    const unsigned char* __restrict__ inv_base,
    float* __restrict__ out)
{
    __shared__ float tile[8 * TILE_PITCH];

    const int lane = threadIdx.x & 31;
    const int w    = threadIdx.x >> 5;         // warp id in CTA = local n
    const int n0   = blockIdx.x * 8;
    const int n    = n0 + w;
    const int b    = lane << 3;

    float acc[8];
    level_math(src, lvl, n, b, weights, biases, parents, inv_base, acc);

    float* tp = tile + w * TILE_PITCH + b;
    *reinterpret_cast<float4*>(tp)     = make_float4(acc[0], acc[1], acc[2], acc[3]);
    *reinterpret_cast<float4*>(tp + 4) = make_float4(acc[4], acc[5], acc[6], acc[7]);
    __syncthreads();

    const int nn = lane & 7;          // 0..7  (n offset)
    const int bq = lane >> 3;         // 0..3  (b offset within group)
#pragma unroll
    for (int j = 0; j < 8; j++) {
        int bb = w * 32 + j * 4 + bq;
        float v = tile[nn * TILE_PITCH + bb];
        out[(size_t)bb * W_SZ + n0 + nn] = v;
    }
}

// ---------------------------------------------------------------------------
// Launch: prior -> 14 intermediate levels -> fused final level, PDL-chained.
// ---------------------------------------------------------------------------
extern "C" void kernel_launch(void* const* d_in, const int* in_sizes, int n_in,
                              void* d_out, int out_size)
{
    const float*         obs     = (const float*)d_in[0];         // [B, W]
    const float*         pw      = (const float*)d_in[1];         // [W]
    const float*         pb      = (const float*)d_in[2];         // [W]
    const float*         weights = (const float*)d_in[3];         // [L-1, W, K]
    const float*         biases  = (const float*)d_in[4];         // [L-1, W]
    const int*           parents = (const int*)d_in[5];           // [L-1, W, K]
    const unsigned char* inv     = (const unsigned char*)d_in[6]; // [L-1, W]
    float*               out     = (float*)d_out;                 // [B, W]

    (void)in_sizes; (void)n_in; (void)out_size;

    // Prior + transpose into g_h[0] (also detects inv_mask element width)
    prior_transpose_kernel<<<dim3(W_SZ / 32, B_SZ / 64), dim3(32, 8)>>>(obs, pw, pb, inv);

    cudaLaunchAttribute attrs[1];
    attrs[0].id = cudaLaunchAttributeProgrammaticStreamSerialization;
    attrs[0].val.programmaticStreamSerializationAllowed = 1;

    // Levels 0..13: ping-pong g_h[0] <-> g_h[1], PDL-chained, 128-thr CTAs.
    const int blocks = (W_SZ * 32) / 128;  // 1024
    for (int l = 0; l < L_SZ - 2; l++) {
        cudaLaunchConfig_t cfg = {};
        cfg.gridDim  = dim3(blocks, 1, 1);
        cfg.blockDim = dim3(128, 1, 1);
        cfg.dynamicSmemBytes = 0;
        cfg.stream = 0;
        cfg.attrs = attrs;
        cfg.numAttrs = 1;
        cudaLaunchKernelEx(&cfg, level_kernel,
            l & 1, l,
            (const float*)(weights + (size_t)l * W_SZ * K_SZ),
            (const float*)(biases  + (size_t)l * W_SZ),
            (const int*)(parents + (size_t)l * W_SZ * K_SZ),
            (const unsigned char*)inv);
    }

    // Level 14: fused final level + output transpose (fp32, direct to out).
    {
        const int l = L_SZ - 2;  // 14
        cudaLaunchConfig_t cfg = {};
        cfg.gridDim  = dim3(W_SZ / 8, 1, 1);   // 512 CTAs x 8 warps
        cfg.blockDim = dim3(256, 1, 1);
        cfg.dynamicSmemBytes = 0;
        cfg.stream = 0;
        cfg.attrs = attrs;
        cfg.numAttrs = 1;
        cudaLaunchKernelEx(&cfg, level_out_kernel,
            l & 1, l,
            (const float*)(weights + (size_t)l * W_SZ * K_SZ),
            (const float*)(biases  + (size_t)l * W_SZ),
            (const int*)(parents + (size_t)l * W_SZ * K_SZ),
            (const unsigned char*)inv,
            out);
    }
}